// round 3
// baseline (speedup 1.0000x reference)
#include <cuda_runtime.h>

// ---------------------------------------------------------------------------
// roi_grid_head: conv0(s2) + 7x conv3x3 + GN/ReLU each, then 2 rounds of
// grid message passing (per-edge depthwise 5x5 + per-edge 64x64 pointwise,
// scatter-add by destination).
//
// Strategy (round 2): correct fp32 implicit-GEMM baseline.
//  - weights pre-transposed each launch into __device__ scratch: Wt[k][co]
//  - conv as GEMM: M = 512*49 pixels, N = 576 co, K = CIN*9 (im2col on the fly)
//  - GN+ReLU in-place, one block per (n, group): 784 contiguous floats
//  - message passing dst-major: one block per (n, p): no atomics, deterministic
// ---------------------------------------------------------------------------

#define NROI   512
#define CIN0   256
#define IHW0   14
#define OHW    7
#define PIX    49
#define NCO    576
#define NP     9
#define NC     64
#define NREST  7
#define KGEMM0 (CIN0 * 9)            // 2304
#define KGEMMR (NCO * 9)             // 5184
#define MTOT   (NROI * PIX)          // 25088  (= 392 * 64 exactly)
#define NGROUP 36
#define GSZ    784                   // 16 ch * 49 pix, contiguous
#define HALF_OUT (NROI * NCO * PIX)  // 14450688

// __device__ scratch (no allocations allowed)
__device__ float g_wt0[KGEMM0 * NCO];          //  5.3 MB
__device__ float g_wtr[NREST * KGEMMR * NCO];  // 83.6 MB
__device__ float g_bufA[HALF_OUT];             // 57.8 MB
__device__ float g_bufB[HALF_OUT];             // 57.8 MB

// edges are dst-major in the reference (_edges loops dst p, nb order up/left/right/down)
__constant__ int c_esrc[24]   = {1,3, 0,2,4, 1,5, 0,4,6, 1,3,5,7, 2,4,8, 3,7, 4,6,8, 5,7};
__constant__ int c_estart[10] = {0,2,5,7,10,14,17,19,22,24};

// ---------------------------------------------------------------------------
// Weight transposes: [co][k] -> [k][co]
// ---------------------------------------------------------------------------
__global__ void __launch_bounds__(256) transpose0_kernel(const float* __restrict__ w) {
    int i = blockIdx.x * 256 + threadIdx.x;          // out-index order (coalesced writes)
    int k = i / NCO;
    int co = i - k * NCO;
    g_wt0[i] = w[co * KGEMM0 + k];
}

__global__ void __launch_bounds__(256) transposeR_kernel(const float* __restrict__ w) {
    int i = blockIdx.x * 256 + threadIdx.x;
    const int per_layer = KGEMMR * NCO;              // 2985984
    int l = i / per_layer;
    int r = i - l * per_layer;
    int k = r / NCO;
    int co = r - k * NCO;
    g_wtr[i] = w[(l * NCO + co) * KGEMMR + k];
}

// ---------------------------------------------------------------------------
// Implicit-GEMM conv: out[n,co,y,x] = sum_{ci,ky,kx} W[co,ci,ky,kx]*in[n,ci,...]
// Block tile: 64 pixels x 64 co, BK=16. 256 threads, 4x4 per thread.
// ---------------------------------------------------------------------------
template<int CIN, int IHW, int STRIDE>
__global__ void __launch_bounds__(256) conv_gemm_kernel(
    const float* __restrict__ in, const float* __restrict__ wt,
    const float* __restrict__ bias, float* __restrict__ out)
{
    __shared__ float As[16][64];
    __shared__ float Bs[16][64];
    const int K = CIN * 9;

    const int tid = threadIdx.x;
    const int m0  = blockIdx.x * 64;
    const int co0 = blockIdx.y * 64;

    // loader mapping: this thread fills As[kkb + 4j][mm] and Bs[kkb + 4j][mm]
    const int mm  = tid & 63;
    const int kkb = tid >> 6;

    const int m    = m0 + mm;                 // m < 25088 always (exact tiling)
    const int nimg = m / PIX;
    const int pix  = m - nimg * PIX;
    const int py   = pix / OHW;
    const int px   = pix - py * OHW;
    const int iy0  = py * STRIDE - 1;
    const int ix0  = px * STRIDE - 1;
    const float* inb = in + nimg * CIN * IHW * IHW;
    const float* wtb = wt + co0 + mm;

    const int tm0 = (tid & 15) << 2;
    const int tn0 = (tid >> 4) << 2;

    float acc[4][4];
#pragma unroll
    for (int i = 0; i < 4; i++)
#pragma unroll
        for (int j = 0; j < 4; j++) acc[i][j] = 0.f;

    for (int k0 = 0; k0 < K; k0 += 16) {
#pragma unroll
        for (int j = 0; j < 4; j++) {
            const int kk  = kkb + j * 4;
            const int k   = k0 + kk;
            const int ci  = k / 9;
            const int tap = k - ci * 9;
            const int ky  = tap / 3;
            const int kx  = tap - ky * 3;
            const int iy  = iy0 + ky;
            const int ix  = ix0 + kx;
            float v = 0.f;
            if ((unsigned)iy < (unsigned)IHW && (unsigned)ix < (unsigned)IHW)
                v = __ldg(&inb[(ci * IHW + iy) * IHW + ix]);
            As[kk][mm] = v;
            Bs[kk][mm] = wtb[(k0 + kk) * NCO];
        }
        __syncthreads();
#pragma unroll
        for (int kk = 0; kk < 16; kk++) {
            float a[4], b[4];
#pragma unroll
            for (int i = 0; i < 4; i++) a[i] = As[kk][tm0 + i];
#pragma unroll
            for (int j = 0; j < 4; j++) b[j] = Bs[kk][tn0 + j];
#pragma unroll
            for (int i = 0; i < 4; i++)
#pragma unroll
                for (int j = 0; j < 4; j++) acc[i][j] += a[i] * b[j];
        }
        __syncthreads();
    }

#pragma unroll
    for (int i = 0; i < 4; i++) {
        const int m2   = m0 + tm0 + i;
        const int n2   = m2 / PIX;
        const int pix2 = m2 - n2 * PIX;
#pragma unroll
        for (int j = 0; j < 4; j++) {
            const int co = co0 + tn0 + j;
            out[(n2 * NCO + co) * PIX + pix2] = acc[i][j] + bias[co];
        }
    }
}

// ---------------------------------------------------------------------------
// GroupNorm(36 groups of 16ch) + affine + ReLU, in-place.
// One block per (n, g): the 784 floats are contiguous.
// ---------------------------------------------------------------------------
__global__ void __launch_bounds__(256) gn_relu_kernel(
    float* __restrict__ buf, const float* __restrict__ sc, const float* __restrict__ bi)
{
    const int blk = blockIdx.x;               // n*36 + g
    const int g   = blk % NGROUP;
    float* base = buf + blk * GSZ;
    const int tid = threadIdx.x;

    float vals[4];
    int cnt = 0;
    float s1 = 0.f, s2 = 0.f;
    for (int e = tid; e < GSZ; e += 256) {
        float x = base[e];
        vals[cnt++] = x;
        s1 += x;
        s2 += x * x;
    }
#pragma unroll
    for (int o = 16; o > 0; o >>= 1) {
        s1 += __shfl_xor_sync(0xffffffff, s1, o);
        s2 += __shfl_xor_sync(0xffffffff, s2, o);
    }
    __shared__ float r1[8], r2[8];
    __shared__ float s_mu, s_inv;
    const int w = tid >> 5, lane = tid & 31;
    if (lane == 0) { r1[w] = s1; r2[w] = s2; }
    __syncthreads();
    if (tid == 0) {
        float a = 0.f, b = 0.f;
#pragma unroll
        for (int i = 0; i < 8; i++) { a += r1[i]; b += r2[i]; }
        float mu  = a * (1.f / GSZ);
        float var = b * (1.f / GSZ) - mu * mu;
        s_mu  = mu;
        s_inv = rsqrtf(var + 1e-5f);
    }
    __syncthreads();
    const float mu = s_mu, inv = s_inv;
    cnt = 0;
    for (int e = tid; e < GSZ; e += 256) {
        const int ch = g * 16 + e / PIX;
        float y = (vals[cnt++] - mu) * inv * sc[ch] + bi[ch];
        base[e] = fmaxf(y, 0.f);
    }
}

// ---------------------------------------------------------------------------
// Message passing, dst-major: one block per (n, p).
//   out[n,p] = pts[n,p] + sum_{edges e into p} PW_e(DW_e(src[n, esrc(e)]))
// DW: per-channel 5x5 pad2; PW: 64x64 per-edge matrix. No atomics.
// ---------------------------------------------------------------------------
__global__ void __launch_bounds__(256) msg_pass_kernel(
    const float* __restrict__ src_feat,   // [N,576,49]
    const float* __restrict__ pts,        // [N,576,49]
    const float* __restrict__ dw_w,       // [24,64,25]
    const float* __restrict__ dw_b,       // [24,64]
    const float* __restrict__ pw_w,       // [24,64,64]  (o, i)
    const float* __restrict__ pw_b,       // [24,64]
    float* __restrict__ outp)             // [N,576,49]
{
    const int n = blockIdx.x;
    const int p = blockIdx.y;
    const int tid = threadIdx.x;

    __shared__ float s_in[NC * PIX];   // 12.25 KB
    __shared__ float s_dw[NC * PIX];   // 12.25 KB
    __shared__ float s_pw[NC * NC];    // 16 KB

    // per-thread accumulator slots: i = tid + 256*k  (3136 = 12*256 + 64)
    float racc[13];
    const float* ptsb = pts + (n * NCO + p * NC) * PIX;
#pragma unroll
    for (int k = 0; k < 13; k++) {
        int i = tid + k * 256;
        if (i < NC * PIX) racc[k] = ptsb[i];
    }

    const int e0 = c_estart[p], e1 = c_estart[p + 1];
    for (int ed = e0; ed < e1; ed++) {
        const int q = c_esrc[ed];
        const float* sb = src_feat + (n * NCO + q * NC) * PIX;
        for (int i = tid; i < NC * PIX; i += 256) s_in[i] = sb[i];
        for (int i = tid; i < NC * NC; i += 256) s_pw[i] = pw_w[ed * NC * NC + i];
        __syncthreads();

        // depthwise 5x5, pad 2
        for (int i = tid; i < NC * PIX; i += 256) {
            const int c = i / PIX;
            const int pix = i - c * PIX;
            const int y = pix / OHW, x = pix - y * OHW;
            const float* wv = dw_w + (ed * NC + c) * 25;
            float a = dw_b[ed * NC + c];
#pragma unroll
            for (int dy = 0; dy < 5; dy++) {
                const int yy = y + dy - 2;
                if ((unsigned)yy < (unsigned)OHW) {
#pragma unroll
                    for (int dx = 0; dx < 5; dx++) {
                        const int xx = x + dx - 2;
                        if ((unsigned)xx < (unsigned)OHW)
                            a += wv[dy * 5 + dx] * s_in[c * PIX + yy * OHW + xx];
                    }
                }
            }
            s_dw[i] = a;
        }
        __syncthreads();

        // pointwise 64x64 per edge + bias, accumulate into racc
#pragma unroll
        for (int k = 0; k < 13; k++) {
            const int i = tid + k * 256;
            if (i < NC * PIX) {
                const int o = i / PIX;
                const int pix = i - o * PIX;
                float a = pw_b[ed * NC + o];
                const float* wr = &s_pw[o * NC];
#pragma unroll 8
                for (int ic = 0; ic < NC; ic++) a += wr[ic] * s_dw[ic * PIX + pix];
                racc[k] += a;
            }
        }
        __syncthreads();   // before s_in/s_pw get overwritten next edge
    }

    float* ob = outp + (n * NCO + p * NC) * PIX;
#pragma unroll
    for (int k = 0; k < 13; k++) {
        int i = tid + k * 256;
        if (i < NC * PIX) ob[i] = racc[k];
    }
}

__global__ void __launch_bounds__(256) copy_kernel(
    const float* __restrict__ s, float* __restrict__ d)
{
    int i = blockIdx.x * 256 + threadIdx.x;
    d[i] = s[i];
}

// ---------------------------------------------------------------------------
extern "C" void kernel_launch(void* const* d_in, const int* in_sizes, int n_in,
                              void* d_out, int out_size)
{
    const float* x       = (const float*)d_in[0];
    const float* conv0_w = (const float*)d_in[1];
    const float* conv0_b = (const float*)d_in[2];
    const float* gn0_s   = (const float*)d_in[3];
    const float* gn0_b   = (const float*)d_in[4];
    const float* convs_w = (const float*)d_in[5];
    const float* convs_b = (const float*)d_in[6];
    const float* gns_s   = (const float*)d_in[7];
    const float* gns_b   = (const float*)d_in[8];
    const float* fo_dw_w = (const float*)d_in[9];
    const float* fo_dw_b = (const float*)d_in[10];
    const float* fo_pw_w = (const float*)d_in[11];
    const float* fo_pw_b = (const float*)d_in[12];
    const float* so_dw_w = (const float*)d_in[13];
    const float* so_dw_b = (const float*)d_in[14];
    const float* so_pw_w = (const float*)d_in[15];
    const float* so_pw_b = (const float*)d_in[16];
    float* out = (float*)d_out;

    float *pA, *pB, *pW0, *pWr;
    cudaGetSymbolAddress((void**)&pA,  g_bufA);
    cudaGetSymbolAddress((void**)&pB,  g_bufB);
    cudaGetSymbolAddress((void**)&pW0, g_wt0);
    cudaGetSymbolAddress((void**)&pWr, g_wtr);

    // 1) transpose weights into [k][co] layout
    transpose0_kernel<<<(KGEMM0 * NCO) / 256, 256>>>(conv0_w);
    transposeR_kernel<<<(NREST * KGEMMR * NCO) / 256, 256>>>(convs_w);

    // 2) conv0 (stride 2) + GN0 + ReLU
    dim3 cgrid(MTOT / 64, NCO / 64);   // (392, 9)
    conv_gemm_kernel<CIN0, IHW0, 2><<<cgrid, 256>>>(x, pW0, conv0_b, pA);
    gn_relu_kernel<<<NROI * NGROUP, 256>>>(pA, gn0_s, gn0_b);

    // 3) 7x [conv3x3 s1 + GN + ReLU], ping-pong A<->B
    float* cur = pA;
    float* nxt = pB;
    for (int l = 0; l < NREST; l++) {
        conv_gemm_kernel<NCO, OHW, 1><<<cgrid, 256>>>(
            cur, pWr + l * KGEMMR * NCO, convs_b + l * NCO, nxt);
        gn_relu_kernel<<<NROI * NGROUP, 256>>>(nxt, gns_s + l * NCO, gns_b + l * NCO);
        float* t = cur; cur = nxt; nxt = t;
    }
    // cur == final h (pB after 7 swaps), nxt is free scratch

    // 4) output half 1: h
    copy_kernel<<<HALF_OUT / 256, 256>>>(cur, out);

    // 5) first-order fusion: fo = pts + msgs(pts)   (pts == h == cur) -> nxt
    dim3 mgrid(NROI, NP);
    msg_pass_kernel<<<mgrid, 256>>>(cur, cur, fo_dw_w, fo_dw_b, fo_pw_w, fo_pw_b, nxt);

    // 6) second-order fusion: so = pts + msgs(fo) -> output half 2
    msg_pass_kernel<<<mgrid, 256>>>(nxt, cur, so_dw_w, so_dw_b, so_pw_w, so_pw_b,
                                    out + HALF_OUT);
}

// round 4
// speedup vs baseline: 1.6480x; 1.6480x over previous
#include <cuda_runtime.h>
#include <cuda_bf16.h>
#include <cstdint>

// ---------------------------------------------------------------------------
// roi_grid_head, round 3: bf16 hi/lo split tensor-core (mma.sync) conv stack.
//   conv as GEMM: M=25088 (pixels), N=576 (co), K=CIN*9 (im2col on the fly)
//   A (activations) gathered from zero-padded packed-bf16 buffers (no predicates)
//   B (weights) pre-transposed + packed once per launch
//   D = Ahi*Bhi + Ahi*Blo + Alo*Bhi  (fp32 accum)  -> fp32-class accuracy
// GN+ReLU fused with next-layer bf16 packing. Message passing unchanged.
// ---------------------------------------------------------------------------

#define NROI   512
#define CIN0   256
#define OHW    7
#define PIX    49
#define NCO    576
#define NP     9
#define NC     64
#define NREST  7
#define KG0    (CIN0 * 9)            // 2304
#define KGR    (NCO * 9)             // 5184
#define MTOT   (NROI * PIX)          // 25088 = 196*128
#define NGROUP 36
#define GSZ    784
#define HALF_OUT (NROI * NCO * PIX)  // 14450688

// __device__ scratch (zero-initialized; padded borders rely on that and are
// never written, so replays are deterministic)
__device__ uint32_t g_x0p[NROI * CIN0 * 256];      // [n][c][16][16] packed hi|lo  134MB
__device__ uint32_t g_actp[NROI * NCO * 81];       // [n][c][9][9]   packed        95.6MB
__device__ uint32_t g_wt0p[KG0 * NCO];             // [k][co] packed                5.3MB
__device__ uint32_t g_wtrp[NREST * KGR * NCO];     // packed                       83.6MB
__device__ float    g_bufA[HALF_OUT];              // fp32 activations             57.8MB
__device__ float    g_bufB[HALF_OUT];              //                              57.8MB

__constant__ int c_esrc[24]   = {1,3, 0,2,4, 1,5, 0,4,6, 1,3,5,7, 2,4,8, 3,7, 4,6,8, 5,7};
__constant__ int c_estart[10] = {0,2,5,7,10,14,17,19,22,24};

// ---------------------------------------------------------------------------
__device__ __forceinline__ uint32_t pack_hilo(float f) {
    __nv_bfloat16 h = __float2bfloat16(f);
    float hf = __bfloat162float(h);
    __nv_bfloat16 l = __float2bfloat16(f - hf);
    return ((uint32_t)__bfloat16_as_ushort(l) << 16) | (uint32_t)__bfloat16_as_ushort(h);
}

__device__ __forceinline__ void mma_bf16(float& c0, float& c1, float& c2, float& c3,
                                         uint32_t a0, uint32_t a1, uint32_t a2, uint32_t a3,
                                         uint32_t b0, uint32_t b1) {
    asm volatile(
        "mma.sync.aligned.m16n8k16.row.col.f32.bf16.bf16.f32 "
        "{%0,%1,%2,%3},{%4,%5,%6,%7},{%8,%9},{%0,%1,%2,%3};\n"
        : "+f"(c0), "+f"(c1), "+f"(c2), "+f"(c3)
        : "r"(a0), "r"(a1), "r"(a2), "r"(a3), "r"(b0), "r"(b1));
}

// ---------------------------------------------------------------------------
// Packing kernels
// ---------------------------------------------------------------------------
__global__ void __launch_bounds__(256) pack_x0_kernel(const float* __restrict__ x) {
    int i = blockIdx.x * 256 + threadIdx.x;        // over 512*256*196
    int n = i / (CIN0 * 196);
    int r = i - n * (CIN0 * 196);
    int c = r / 196;
    int pix = r - c * 196;
    int y = pix / 14, xx = pix - y * 14;
    g_x0p[((n * CIN0 + c) << 8) + (y + 1) * 16 + (xx + 1)] = pack_hilo(x[i]);
}

__global__ void __launch_bounds__(256) pack_w0_kernel(const float* __restrict__ w) {
    int i = blockIdx.x * 256 + threadIdx.x;        // over 2304*576
    int k = i / NCO, co = i - k * NCO;
    g_wt0p[i] = pack_hilo(w[co * KG0 + k]);
}

__global__ void __launch_bounds__(256) pack_wr_kernel(const float* __restrict__ w) {
    int i = blockIdx.x * 256 + threadIdx.x;        // over 7*5184*576
    const int per = KGR * NCO;
    int l = i / per;
    int r = i - l * per;
    int k = r / NCO, co = r - k * NCO;
    g_wtrp[i] = pack_hilo(w[(l * NCO + co) * KGR + k]);
}

// ---------------------------------------------------------------------------
// Tensor-core implicit-GEMM conv. Block 128(M)x64(N), BK=32, 256 threads.
// Warp grid 4(M)x2(N): warp tile 32x32 = 2 m16 x 4 n8 mma tiles.
// IS0: conv0 mode (input g_x0p, 16x16 padded, stride 2); else g_actp 9x9 pad.
// ---------------------------------------------------------------------------
template<int CIN, int K, bool IS0>
__global__ void __launch_bounds__(256, 2) conv_mma_kernel(
    const uint32_t* __restrict__ act, const uint32_t* __restrict__ wt,
    const float* __restrict__ bias, float* __restrict__ out)
{
    constexpr int IAREA  = IS0 ? 256 : 81;
    constexpr int IPITCH = IS0 ? 16 : 9;
    constexpr int SSTR   = 40;   // smem row stride (bf16 units), conflict-free frags

    __shared__ unsigned short As_hi[128 * SSTR];
    __shared__ unsigned short As_lo[128 * SSTR];
    __shared__ unsigned short Bs_hi[64 * SSTR];
    __shared__ unsigned short Bs_lo[64 * SSTR];

    const int tid  = threadIdx.x;
    const int m0   = blockIdx.x * 128;
    const int co0  = blockIdx.y * 64;
    const int warp = tid >> 5;
    const int lane = tid & 31;
    const int wm   = warp >> 1;          // 0..3 -> m offset wm*32
    const int wn   = warp & 1;           // 0..1 -> n offset wn*32
    const int grp  = lane >> 2;          // mma group id
    const int tg   = lane & 3;

    // ---- A loader fixed mapping: kk = tid&31, rows = (tid>>5) + 8*it ----
    const int kkA   = tid & 31;
    const int rbase = tid >> 5;
    int obase[16];
#pragma unroll
    for (int it = 0; it < 16; it++) {
        int m    = m0 + rbase + 8 * it;
        int nimg = m / PIX;
        int pix  = m - nimg * PIX;
        int y    = pix / OHW;
        int x    = pix - y * OHW;
        if (IS0) obase[it] = nimg * (CIN0 * 256) + (2 * y) * 16 + 2 * x;
        else     obase[it] = nimg * (NCO * 81) + y * 9 + x;
    }
    // ---- B loader: nn = tid&63, kk = (tid>>6) + 4*it ----
    const int nnB  = tid & 63;
    const int kkB0 = tid >> 6;

    float acc[2][4][4];
#pragma unroll
    for (int a = 0; a < 2; a++)
#pragma unroll
        for (int b = 0; b < 4; b++)
#pragma unroll
            for (int c = 0; c < 4; c++) acc[a][b][c] = 0.f;

    for (int k0 = 0; k0 < K; k0 += 32) {
        // ---- load A tile (128x32) ----
        {
            int k   = k0 + kkA;
            int ci  = k / 9;
            int tap = k - ci * 9;
            int ky  = tap / 3;
            int kx  = tap - ky * 3;
            int koff = ci * IAREA + ky * IPITCH + kx;
#pragma unroll
            for (int it = 0; it < 16; it++) {
                uint32_t v = __ldg(&act[obase[it] + koff]);
                int s = (rbase + 8 * it) * SSTR + kkA;
                As_hi[s] = (unsigned short)(v & 0xffffu);
                As_lo[s] = (unsigned short)(v >> 16);
            }
        }
        // ---- load B tile (64x32) ----
#pragma unroll
        for (int it = 0; it < 8; it++) {
            int kk = kkB0 + 4 * it;
            uint32_t v = __ldg(&wt[(k0 + kk) * NCO + co0 + nnB]);
            int s = nnB * SSTR + kk;
            Bs_hi[s] = (unsigned short)(v & 0xffffu);
            Bs_lo[s] = (unsigned short)(v >> 16);
        }
        __syncthreads();

        // ---- compute: two k16 halves ----
#pragma unroll
        for (int h = 0; h < 32; h += 16) {
            uint32_t Ah[2][4], Al[2][4], Bh[4][2], Bl[4][2];
            const int colb = h + 2 * tg;
#pragma unroll
            for (int mi = 0; mi < 2; mi++) {
                int r = wm * 32 + mi * 16 + grp;
                Ah[mi][0] = *(const uint32_t*)&As_hi[r * SSTR + colb];
                Ah[mi][1] = *(const uint32_t*)&As_hi[(r + 8) * SSTR + colb];
                Ah[mi][2] = *(const uint32_t*)&As_hi[r * SSTR + colb + 8];
                Ah[mi][3] = *(const uint32_t*)&As_hi[(r + 8) * SSTR + colb + 8];
                Al[mi][0] = *(const uint32_t*)&As_lo[r * SSTR + colb];
                Al[mi][1] = *(const uint32_t*)&As_lo[(r + 8) * SSTR + colb];
                Al[mi][2] = *(const uint32_t*)&As_lo[r * SSTR + colb + 8];
                Al[mi][3] = *(const uint32_t*)&As_lo[(r + 8) * SSTR + colb + 8];
            }
#pragma unroll
            for (int ni = 0; ni < 4; ni++) {
                int nrow = wn * 32 + ni * 8 + grp;
                Bh[ni][0] = *(const uint32_t*)&Bs_hi[nrow * SSTR + colb];
                Bh[ni][1] = *(const uint32_t*)&Bs_hi[nrow * SSTR + colb + 8];
                Bl[ni][0] = *(const uint32_t*)&Bs_lo[nrow * SSTR + colb];
                Bl[ni][1] = *(const uint32_t*)&Bs_lo[nrow * SSTR + colb + 8];
            }
#pragma unroll
            for (int mi = 0; mi < 2; mi++)
#pragma unroll
                for (int ni = 0; ni < 4; ni++) {
                    float* c = acc[mi][ni];
                    mma_bf16(c[0], c[1], c[2], c[3],
                             Ah[mi][0], Ah[mi][1], Ah[mi][2], Ah[mi][3],
                             Bh[ni][0], Bh[ni][1]);
                    mma_bf16(c[0], c[1], c[2], c[3],
                             Ah[mi][0], Ah[mi][1], Ah[mi][2], Ah[mi][3],
                             Bl[ni][0], Bl[ni][1]);
                    mma_bf16(c[0], c[1], c[2], c[3],
                             Al[mi][0], Al[mi][1], Al[mi][2], Al[mi][3],
                             Bh[ni][0], Bh[ni][1]);
                }
        }
        __syncthreads();
    }

    // ---- epilogue: out[(nimg*576+co)*49 + pix] = acc + bias ----
#pragma unroll
    for (int mi = 0; mi < 2; mi++) {
#pragma unroll
        for (int half = 0; half < 2; half++) {
            int m    = m0 + wm * 32 + mi * 16 + grp + 8 * half;
            int nimg = m / PIX;
            int pix  = m - nimg * PIX;
            float* ob = out + (nimg * NCO) * PIX + pix;
#pragma unroll
            for (int ni = 0; ni < 4; ni++) {
                int co = co0 + wn * 32 + ni * 8 + 2 * tg;
                float b0 = __ldg(&bias[co]);
                float b1 = __ldg(&bias[co + 1]);
                ob[co * PIX]       = acc[mi][ni][2 * half]     + b0;
                ob[(co + 1) * PIX] = acc[mi][ni][2 * half + 1] + b1;
            }
        }
    }
}

// ---------------------------------------------------------------------------
// GroupNorm + affine + ReLU (in-place fp32) + pack bf16 hi/lo into g_actp.
// One block per (n, group): 784 contiguous floats.
// ---------------------------------------------------------------------------
__global__ void __launch_bounds__(256) gn_relu_pack_kernel(
    float* __restrict__ buf, const float* __restrict__ sc, const float* __restrict__ bi,
    uint32_t* __restrict__ packed)
{
    const int blk = blockIdx.x;
    const int n   = blk / NGROUP;
    const int g   = blk - n * NGROUP;
    float* base = buf + blk * GSZ;
    const int tid = threadIdx.x;

    float vals[4];
    int cnt = 0;
    float s1 = 0.f, s2 = 0.f;
    for (int e = tid; e < GSZ; e += 256) {
        float x = base[e];
        vals[cnt++] = x;
        s1 += x; s2 += x * x;
    }
#pragma unroll
    for (int o = 16; o > 0; o >>= 1) {
        s1 += __shfl_xor_sync(0xffffffff, s1, o);
        s2 += __shfl_xor_sync(0xffffffff, s2, o);
    }
    __shared__ float r1[8], r2[8];
    __shared__ float s_mu, s_inv;
    const int w = tid >> 5, lane = tid & 31;
    if (lane == 0) { r1[w] = s1; r2[w] = s2; }
    __syncthreads();
    if (tid == 0) {
        float a = 0.f, b = 0.f;
#pragma unroll
        for (int i = 0; i < 8; i++) { a += r1[i]; b += r2[i]; }
        float mu  = a * (1.f / GSZ);
        float var = b * (1.f / GSZ) - mu * mu;
        s_mu = mu;
        s_inv = rsqrtf(var + 1e-5f);
    }
    __syncthreads();
    const float mu = s_mu, inv = s_inv;
    cnt = 0;
    for (int e = tid; e < GSZ; e += 256) {
        const int chl = e / PIX;
        const int pix = e - chl * PIX;
        const int ch  = g * 16 + chl;
        float y = (vals[cnt++] - mu) * inv * sc[ch] + bi[ch];
        y = fmaxf(y, 0.f);
        base[e] = y;
        const int py = pix / OHW, px = pix - py * OHW;
        packed[(n * NCO + ch) * 81 + (py + 1) * 9 + (px + 1)] = pack_hilo(y);
    }
}

// ---------------------------------------------------------------------------
// Message passing, dst-major (unchanged from round 2 — correct + cheap).
// ---------------------------------------------------------------------------
__global__ void __launch_bounds__(256) msg_pass_kernel(
    const float* __restrict__ src_feat, const float* __restrict__ pts,
    const float* __restrict__ dw_w, const float* __restrict__ dw_b,
    const float* __restrict__ pw_w, const float* __restrict__ pw_b,
    float* __restrict__ outp)
{
    const int n = blockIdx.x;
    const int p = blockIdx.y;
    const int tid = threadIdx.x;

    __shared__ float s_in[NC * PIX];
    __shared__ float s_dw[NC * PIX];
    __shared__ float s_pw[NC * NC];

    float racc[13];
    const float* ptsb = pts + (n * NCO + p * NC) * PIX;
#pragma unroll
    for (int k = 0; k < 13; k++) {
        int i = tid + k * 256;
        if (i < NC * PIX) racc[k] = ptsb[i];
    }

    const int e0 = c_estart[p], e1 = c_estart[p + 1];
    for (int ed = e0; ed < e1; ed++) {
        const int q = c_esrc[ed];
        const float* sb = src_feat + (n * NCO + q * NC) * PIX;
        for (int i = tid; i < NC * PIX; i += 256) s_in[i] = sb[i];
        for (int i = tid; i < NC * NC; i += 256) s_pw[i] = pw_w[ed * NC * NC + i];
        __syncthreads();

        for (int i = tid; i < NC * PIX; i += 256) {
            const int c = i / PIX;
            const int pix = i - c * PIX;
            const int y = pix / OHW, x = pix - y * OHW;
            const float* wv = dw_w + (ed * NC + c) * 25;
            float a = dw_b[ed * NC + c];
#pragma unroll
            for (int dy = 0; dy < 5; dy++) {
                const int yy = y + dy - 2;
                if ((unsigned)yy < (unsigned)OHW) {
#pragma unroll
                    for (int dx = 0; dx < 5; dx++) {
                        const int xx = x + dx - 2;
                        if ((unsigned)xx < (unsigned)OHW)
                            a += wv[dy * 5 + dx] * s_in[c * PIX + yy * OHW + xx];
                    }
                }
            }
            s_dw[i] = a;
        }
        __syncthreads();

#pragma unroll
        for (int k = 0; k < 13; k++) {
            const int i = tid + k * 256;
            if (i < NC * PIX) {
                const int o = i / PIX;
                const int pix = i - o * PIX;
                float a = pw_b[ed * NC + o];
                const float* wr = &s_pw[o * NC];
#pragma unroll 8
                for (int ic = 0; ic < NC; ic++) a += wr[ic] * s_dw[ic * PIX + pix];
                racc[k] += a;
            }
        }
        __syncthreads();
    }

    float* ob = outp + (n * NCO + p * NC) * PIX;
#pragma unroll
    for (int k = 0; k < 13; k++) {
        int i = tid + k * 256;
        if (i < NC * PIX) ob[i] = racc[k];
    }
}

__global__ void __launch_bounds__(256) copy_kernel(
    const float* __restrict__ s, float* __restrict__ d)
{
    int i = blockIdx.x * 256 + threadIdx.x;
    d[i] = s[i];
}

// ---------------------------------------------------------------------------
extern "C" void kernel_launch(void* const* d_in, const int* in_sizes, int n_in,
                              void* d_out, int out_size)
{
    const float* x       = (const float*)d_in[0];
    const float* conv0_w = (const float*)d_in[1];
    const float* conv0_b = (const float*)d_in[2];
    const float* gn0_s   = (const float*)d_in[3];
    const float* gn0_b   = (const float*)d_in[4];
    const float* convs_w = (const float*)d_in[5];
    const float* convs_b = (const float*)d_in[6];
    const float* gns_s   = (const float*)d_in[7];
    const float* gns_b   = (const float*)d_in[8];
    const float* fo_dw_w = (const float*)d_in[9];
    const float* fo_dw_b = (const float*)d_in[10];
    const float* fo_pw_w = (const float*)d_in[11];
    const float* fo_pw_b = (const float*)d_in[12];
    const float* so_dw_w = (const float*)d_in[13];
    const float* so_dw_b = (const float*)d_in[14];
    const float* so_pw_w = (const float*)d_in[15];
    const float* so_pw_b = (const float*)d_in[16];
    float* out = (float*)d_out;

    float *pA, *pB;
    uint32_t *pX0, *pAct, *pW0, *pWr;
    cudaGetSymbolAddress((void**)&pA,   g_bufA);
    cudaGetSymbolAddress((void**)&pB,   g_bufB);
    cudaGetSymbolAddress((void**)&pX0,  g_x0p);
    cudaGetSymbolAddress((void**)&pAct, g_actp);
    cudaGetSymbolAddress((void**)&pW0,  g_wt0p);
    cudaGetSymbolAddress((void**)&pWr,  g_wtrp);

    // 1) pack inputs & weights to bf16 hi/lo
    pack_x0_kernel<<<(NROI * CIN0 * 196) / 256, 256>>>(x);
    pack_w0_kernel<<<(KG0 * NCO) / 256, 256>>>(conv0_w);
    pack_wr_kernel<<<(NREST * KGR * NCO) / 256, 256>>>(convs_w);

    dim3 cgrid(MTOT / 128, NCO / 64);   // (196, 9)

    // 2) conv0 (stride 2) + GN0/ReLU (+repack)
    conv_mma_kernel<CIN0, KG0, true><<<cgrid, 256>>>(pX0, pW0, conv0_b, pA);
    gn_relu_pack_kernel<<<NROI * NGROUP, 256>>>(pA, gn0_s, gn0_b, pAct);

    // 3) 7x [conv3x3 + GN/ReLU(+repack)], ping-pong
    float* cur = pA;
    float* nxt = pB;
    for (int l = 0; l < NREST; l++) {
        conv_mma_kernel<NCO, KGR, false><<<cgrid, 256>>>(
            pAct, pWr + l * KGR * NCO, convs_b + l * NCO, nxt);
        gn_relu_pack_kernel<<<NROI * NGROUP, 256>>>(nxt, gns_s + l * NCO, gns_b + l * NCO, pAct);
        float* t = cur; cur = nxt; nxt = t;
    }
    // cur == final h, nxt free

    // 4) output half 1: h
    copy_kernel<<<HALF_OUT / 256, 256>>>(cur, out);

    // 5) first-order fusion -> nxt
    dim3 mgrid(NROI, NP);
    msg_pass_kernel<<<mgrid, 256>>>(cur, cur, fo_dw_w, fo_dw_b, fo_pw_w, fo_pw_b, nxt);

    // 6) second-order fusion -> output half 2
    msg_pass_kernel<<<mgrid, 256>>>(nxt, cur, so_dw_w, so_dw_b, so_pw_w, so_pw_b,
                                    out + HALF_OUT);
}

// round 5
// speedup vs baseline: 2.0160x; 1.2233x over previous
#include <cuda_runtime.h>
#include <cuda_bf16.h>
#include <cstdint>

// ---------------------------------------------------------------------------
// roi_grid_head, round 4: pure-GEMM conv via explicit im2col planes (bf16
// hi/lo split), cp.async 3-stage pipeline, ldmatrix fragment loads.
//   D = Ahi*Bhi + Ahi*Blo + Alo*Bhi  (fp32 accum)
// ---------------------------------------------------------------------------

#define NROI   512
#define CIN0   256
#define OHW    7
#define PIX    49
#define NCO    576
#define NP     9
#define NC     64
#define NREST  7
#define KG0    (CIN0 * 9)            // 2304
#define KGR    (NCO * 9)             // 5184
#define MTOT   (NROI * PIX)          // 25088 = 196*128
#define NGROUP 36
#define GSZ    784
#define HALF_OUT (NROI * NCO * PIX)  // 14450688

#define BM 128
#define BN 64
#define BK 32
#define SSTR 40                       // smem row stride in bf16 units (80B)

// __device__ scratch (zero-initialized; padded borders never written)
__device__ unsigned short g_colh[(size_t)MTOT * KGR];   // im2col hi plane  260MB
__device__ unsigned short g_coll[(size_t)MTOT * KGR];   // im2col lo plane  260MB
__device__ unsigned short g_acth[NROI * NCO * 81];      // act hi [n][c][9][9] pad1
__device__ unsigned short g_actl[NROI * NCO * 81];
__device__ unsigned short g_x0h[NROI * CIN0 * 256];     // x hi [n][c][16][16] pad1
__device__ unsigned short g_x0l[NROI * CIN0 * 256];
__device__ unsigned short g_w0h[NCO * KG0];             // [co][k] hi
__device__ unsigned short g_w0l[NCO * KG0];
__device__ unsigned short g_wrh[NREST * NCO * KGR];
__device__ unsigned short g_wrl[NREST * NCO * KGR];
__device__ float g_bufA[HALF_OUT];
__device__ float g_bufB[HALF_OUT];

__constant__ int c_esrc[24]   = {1,3, 0,2,4, 1,5, 0,4,6, 1,3,5,7, 2,4,8, 3,7, 4,6,8, 5,7};
__constant__ int c_estart[10] = {0,2,5,7,10,14,17,19,22,24};

// ---------------------------------------------------------------------------
__device__ __forceinline__ void split_bf(float f, unsigned short& h, unsigned short& l) {
    __nv_bfloat16 bh = __float2bfloat16(f);
    float r = f - __bfloat162float(bh);
    h = __bfloat16_as_ushort(bh);
    l = __bfloat16_as_ushort(__float2bfloat16(r));
}

__device__ __forceinline__ void mma_bf16(float& c0, float& c1, float& c2, float& c3,
                                         uint32_t a0, uint32_t a1, uint32_t a2, uint32_t a3,
                                         uint32_t b0, uint32_t b1) {
    asm volatile(
        "mma.sync.aligned.m16n8k16.row.col.f32.bf16.bf16.f32 "
        "{%0,%1,%2,%3},{%4,%5,%6,%7},{%8,%9},{%0,%1,%2,%3};\n"
        : "+f"(c0), "+f"(c1), "+f"(c2), "+f"(c3)
        : "r"(a0), "r"(a1), "r"(a2), "r"(a3), "r"(b0), "r"(b1));
}

__device__ __forceinline__ void ldmx4(uint32_t& r0, uint32_t& r1, uint32_t& r2, uint32_t& r3,
                                      uint32_t addr) {
    asm volatile("ldmatrix.sync.aligned.m8n8.x4.shared.b16 {%0,%1,%2,%3},[%4];\n"
                 : "=r"(r0), "=r"(r1), "=r"(r2), "=r"(r3) : "r"(addr));
}

__device__ __forceinline__ void cp16(uint32_t daddr, const void* src) {
    asm volatile("cp.async.cg.shared.global [%0], [%1], 16;\n" :: "r"(daddr), "l"(src));
}
__device__ __forceinline__ void cp_commit() { asm volatile("cp.async.commit_group;\n" ::: "memory"); }
__device__ __forceinline__ void cp_wait1()  { asm volatile("cp.async.wait_group 1;\n" ::: "memory"); }

// ---------------------------------------------------------------------------
// Packing / im2col kernels
// ---------------------------------------------------------------------------
__global__ void __launch_bounds__(256) pack_x0_kernel(const float* __restrict__ x) {
    int i = blockIdx.x * 256 + threadIdx.x;       // 512*256*196
    int n = i / (CIN0 * 196);
    int r = i - n * (CIN0 * 196);
    int c = r / 196;
    int pix = r - c * 196;
    int y = pix / 14, xx = pix - y * 14;
    unsigned short h, l;
    split_bf(x[i], h, l);
    int o = ((n * CIN0 + c) << 8) + (y + 1) * 16 + (xx + 1);
    g_x0h[o] = h; g_x0l[o] = l;
}

__global__ void __launch_bounds__(256) pack_split_kernel(
    const float* __restrict__ w, unsigned short* __restrict__ ph,
    unsigned short* __restrict__ pl) {
    int i = blockIdx.x * 256 + threadIdx.x;
    unsigned short h, l;
    split_bf(w[i], h, l);
    ph[i] = h; pl[i] = l;
}

// im2col: writes [m][K] hi/lo planes. IS0: read padded 16x16 stride-2 x0 planes
// else padded 9x9 act planes.
template<int K, bool IS0>
__global__ void __launch_bounds__(256) im2col_kernel(
    const unsigned short* __restrict__ ah, const unsigned short* __restrict__ al,
    unsigned short* __restrict__ ch, unsigned short* __restrict__ cl) {
    const int KQ = K / 4;
    int i = blockIdx.x * 256 + threadIdx.x;       // MTOT * KQ
    int m  = i / KQ;
    int kq = (i - m * KQ) * 4;
    int nimg = m / PIX, pix = m - nimg * PIX;
    int y = pix / OHW, x = pix - y * OHW;
    unsigned short hs[4], ls[4];
#pragma unroll
    for (int j = 0; j < 4; j++) {
        int k = kq + j;
        int ci = k / 9, tap = k - ci * 9;
        int ky = tap / 3, kx = tap - ky * 3;
        int idx;
        if (IS0) idx = ((nimg * CIN0 + ci) << 8) + (2 * y + ky) * 16 + (2 * x + kx);
        else     idx = (nimg * NCO + ci) * 81 + (y + ky) * 9 + (x + kx);
        hs[j] = ah[idx];
        ls[j] = al[idx];
    }
    size_t o = (size_t)m * K + kq;
    *(ushort4*)&ch[o] = make_ushort4(hs[0], hs[1], hs[2], hs[3]);
    *(ushort4*)&cl[o] = make_ushort4(ls[0], ls[1], ls[2], ls[3]);
}

// ---------------------------------------------------------------------------
// Pure GEMM: out[m][co] (scattered to NCHW) = A[m][K] * B[co][K]^T
// BM=128 BN=64 BK=32, 3-stage cp.async, ldmatrix fragments, hi/lo split.
// grid = (NCO/BN, MTOT/BM): n fastest for A L2 reuse.
// ---------------------------------------------------------------------------
template<int K>
__global__ void __launch_bounds__(256, 2) conv_gemm_kernel(
    const unsigned short* __restrict__ Agh, const unsigned short* __restrict__ Agl,
    const unsigned short* __restrict__ Bgh, const unsigned short* __restrict__ Bgl,
    const float* __restrict__ bias, float* __restrict__ out)
{
    extern __shared__ unsigned short smem[];
    constexpr int A_SZ = BM * SSTR;               // 5120 u16
    constexpr int B_SZ = BN * SSTR;               // 2560 u16
    constexpr int STG  = 2 * A_SZ + 2 * B_SZ;     // 15360 u16 per stage
    constexpr int T    = K / BK;

    const int tid  = threadIdx.x;
    const int lane = tid & 31;
    const int warp = tid >> 5;
    const int wm = warp >> 1, wn = warp & 1;
    const int grp = lane >> 2, tg = lane & 3;
    const int co0 = blockIdx.x * BN;
    const int m0  = blockIdx.y * BM;

    const uint32_t smem_b = (uint32_t)__cvta_generic_to_shared(smem);

    // loader mapping
    const int ar = tid >> 1;                      // A row 0..127
    const int ac = (tid & 1) * 16;                // A k-offset {0,16}
    const int br = tid & 63;                      // B row 0..63
    const int bc = (tid >> 6) * 8;                // B k-offset {0,8,16,24}
    const unsigned short* Agh_p = Agh + (size_t)(m0 + ar) * K;
    const unsigned short* Agl_p = Agl + (size_t)(m0 + ar) * K;
    const unsigned short* Bgh_p = Bgh + (size_t)(co0 + br) * K;
    const unsigned short* Bgl_p = Bgl + (size_t)(co0 + br) * K;
    const uint32_t sAo = (uint32_t)(ar * SSTR * 2);
    const uint32_t sBo = (uint32_t)(br * SSTR * 2);

    // ldmatrix per-thread byte offsets within plane
    const uint32_t offA = (uint32_t)(((wm * 32 + (lane & 15)) * SSTR + 8 * (lane >> 4)) * 2);
    const uint32_t offB = (uint32_t)(((wn * 32 + (lane & 7) + 8 * (lane >> 4)) * SSTR
                                      + 8 * ((lane >> 3) & 1)) * 2);

    float acc[2][4][4];
#pragma unroll
    for (int a = 0; a < 2; a++)
#pragma unroll
        for (int b = 0; b < 4; b++)
#pragma unroll
            for (int c = 0; c < 4; c++) acc[a][b][c] = 0.f;

#define ISSUE(t_)                                                              \
    do {                                                                       \
        int t__ = (t_);                                                        \
        if (t__ < T) {                                                         \
            const uint32_t sb = smem_b + (uint32_t)((t__ % 3) * STG) * 2;      \
            const int kt = t__ * BK;                                           \
            cp16(sb + sAo + ac * 2,             Agh_p + kt + ac);              \
            cp16(sb + sAo + (ac + 8) * 2,       Agh_p + kt + ac + 8);          \
            cp16(sb + A_SZ * 2 + sAo + ac * 2,       Agl_p + kt + ac);         \
            cp16(sb + A_SZ * 2 + sAo + (ac + 8) * 2, Agl_p + kt + ac + 8);     \
            cp16(sb + 2 * A_SZ * 2 + sBo + bc * 2,           Bgh_p + kt + bc); \
            cp16(sb + (2 * A_SZ + B_SZ) * 2 + sBo + bc * 2,  Bgl_p + kt + bc); \
        }                                                                      \
        cp_commit();                                                           \
    } while (0)

    ISSUE(0);
    ISSUE(1);

    for (int t = 0; t < T; t++) {
        cp_wait1();
        __syncthreads();
        ISSUE(t + 2);

        const uint32_t aH = smem_b + (uint32_t)((t % 3) * STG) * 2;
        const uint32_t aL = aH + A_SZ * 2;
        const uint32_t bH = aH + 2 * A_SZ * 2;
        const uint32_t bL = bH + B_SZ * 2;

#pragma unroll
        for (int h = 0; h < BK; h += 16) {
            uint32_t Af[2][4], Lf[2][4], Bf[4][2], Mf[4][2];
#pragma unroll
            for (int mi = 0; mi < 2; mi++) {
                const uint32_t d = offA + (uint32_t)((mi * 16 * SSTR + h) * 2);
                ldmx4(Af[mi][0], Af[mi][1], Af[mi][2], Af[mi][3], aH + d);
                ldmx4(Lf[mi][0], Lf[mi][1], Lf[mi][2], Lf[mi][3], aL + d);
            }
#pragma unroll
            for (int np = 0; np < 2; np++) {
                const uint32_t d = offB + (uint32_t)((np * 16 * SSTR + h) * 2);
                ldmx4(Bf[2*np][0], Bf[2*np][1], Bf[2*np+1][0], Bf[2*np+1][1], bH + d);
                ldmx4(Mf[2*np][0], Mf[2*np][1], Mf[2*np+1][0], Mf[2*np+1][1], bL + d);
            }
#pragma unroll
            for (int mi = 0; mi < 2; mi++)
#pragma unroll
                for (int ni = 0; ni < 4; ni++) {
                    float* c = acc[mi][ni];
                    mma_bf16(c[0], c[1], c[2], c[3],
                             Af[mi][0], Af[mi][1], Af[mi][2], Af[mi][3],
                             Bf[ni][0], Bf[ni][1]);
                    mma_bf16(c[0], c[1], c[2], c[3],
                             Af[mi][0], Af[mi][1], Af[mi][2], Af[mi][3],
                             Mf[ni][0], Mf[ni][1]);
                    mma_bf16(c[0], c[1], c[2], c[3],
                             Lf[mi][0], Lf[mi][1], Lf[mi][2], Lf[mi][3],
                             Bf[ni][0], Bf[ni][1]);
                }
        }
    }
#undef ISSUE

    // epilogue: out[(nimg*576+co)*49 + pix] = acc + bias
#pragma unroll
    for (int mi = 0; mi < 2; mi++) {
#pragma unroll
        for (int half = 0; half < 2; half++) {
            int m    = m0 + wm * 32 + mi * 16 + grp + 8 * half;
            int nimg = m / PIX;
            int pix  = m - nimg * PIX;
            float* ob = out + (size_t)(nimg * NCO) * PIX + pix;
#pragma unroll
            for (int ni = 0; ni < 4; ni++) {
                int co = co0 + wn * 32 + ni * 8 + 2 * tg;
                float b0 = __ldg(&bias[co]);
                float b1 = __ldg(&bias[co + 1]);
                ob[(size_t)co * PIX]       = acc[mi][ni][2 * half]     + b0;
                ob[(size_t)(co + 1) * PIX] = acc[mi][ni][2 * half + 1] + b1;
            }
        }
    }
}

// ---------------------------------------------------------------------------
// GroupNorm + affine + ReLU (in-place fp32) + write bf16 hi/lo padded planes.
// ---------------------------------------------------------------------------
__global__ void __launch_bounds__(256) gn_relu_pack_kernel(
    float* __restrict__ buf, const float* __restrict__ sc, const float* __restrict__ bi,
    unsigned short* __restrict__ ph, unsigned short* __restrict__ pl)
{
    const int blk = blockIdx.x;
    const int n   = blk / NGROUP;
    const int g   = blk - n * NGROUP;
    float* base = buf + (size_t)blk * GSZ;
    const int tid = threadIdx.x;

    float vals[4];
    int cnt = 0;
    float s1 = 0.f, s2 = 0.f;
    for (int e = tid; e < GSZ; e += 256) {
        float x = base[e];
        vals[cnt++] = x;
        s1 += x; s2 += x * x;
    }
#pragma unroll
    for (int o = 16; o > 0; o >>= 1) {
        s1 += __shfl_xor_sync(0xffffffff, s1, o);
        s2 += __shfl_xor_sync(0xffffffff, s2, o);
    }
    __shared__ float r1[8], r2[8];
    __shared__ float s_mu, s_inv;
    const int w = tid >> 5, lane = tid & 31;
    if (lane == 0) { r1[w] = s1; r2[w] = s2; }
    __syncthreads();
    if (tid == 0) {
        float a = 0.f, b = 0.f;
#pragma unroll
        for (int i = 0; i < 8; i++) { a += r1[i]; b += r2[i]; }
        float mu  = a * (1.f / GSZ);
        float var = b * (1.f / GSZ) - mu * mu;
        s_mu = mu;
        s_inv = rsqrtf(var + 1e-5f);
    }
    __syncthreads();
    const float mu = s_mu, inv = s_inv;
    cnt = 0;
    for (int e = tid; e < GSZ; e += 256) {
        const int chl = e / PIX;
        const int pix = e - chl * PIX;
        const int ch  = g * 16 + chl;
        float y = (vals[cnt++] - mu) * inv * sc[ch] + bi[ch];
        y = fmaxf(y, 0.f);
        base[e] = y;
        const int py = pix / OHW, px = pix - py * OHW;
        unsigned short hh, ll;
        split_bf(y, hh, ll);
        const int o = (n * NCO + ch) * 81 + (py + 1) * 9 + (px + 1);
        ph[o] = hh; pl[o] = ll;
    }
}

// ---------------------------------------------------------------------------
// Message passing, dst-major (unchanged — correct + cheap).
// ---------------------------------------------------------------------------
__global__ void __launch_bounds__(256) msg_pass_kernel(
    const float* __restrict__ src_feat, const float* __restrict__ pts,
    const float* __restrict__ dw_w, const float* __restrict__ dw_b,
    const float* __restrict__ pw_w, const float* __restrict__ pw_b,
    float* __restrict__ outp)
{
    const int n = blockIdx.x;
    const int p = blockIdx.y;
    const int tid = threadIdx.x;

    __shared__ float s_in[NC * PIX];
    __shared__ float s_dw[NC * PIX];
    __shared__ float s_pw[NC * NC];

    float racc[13];
    const float* ptsb = pts + (size_t)(n * NCO + p * NC) * PIX;
#pragma unroll
    for (int k = 0; k < 13; k++) {
        int i = tid + k * 256;
        if (i < NC * PIX) racc[k] = ptsb[i];
    }

    const int e0 = c_estart[p], e1 = c_estart[p + 1];
    for (int ed = e0; ed < e1; ed++) {
        const int q = c_esrc[ed];
        const float* sb = src_feat + (size_t)(n * NCO + q * NC) * PIX;
        for (int i = tid; i < NC * PIX; i += 256) s_in[i] = sb[i];
        for (int i = tid; i < NC * NC; i += 256) s_pw[i] = pw_w[ed * NC * NC + i];
        __syncthreads();

        for (int i = tid; i < NC * PIX; i += 256) {
            const int c = i / PIX;
            const int pix = i - c * PIX;
            const int y = pix / OHW, x = pix - y * OHW;
            const float* wv = dw_w + (ed * NC + c) * 25;
            float a = dw_b[ed * NC + c];
#pragma unroll
            for (int dy = 0; dy < 5; dy++) {
                const int yy = y + dy - 2;
                if ((unsigned)yy < (unsigned)OHW) {
#pragma unroll
                    for (int dx = 0; dx < 5; dx++) {
                        const int xx = x + dx - 2;
                        if ((unsigned)xx < (unsigned)OHW)
                            a += wv[dy * 5 + dx] * s_in[c * PIX + yy * OHW + xx];
                    }
                }
            }
            s_dw[i] = a;
        }
        __syncthreads();

#pragma unroll
        for (int k = 0; k < 13; k++) {
            const int i = tid + k * 256;
            if (i < NC * PIX) {
                const int o = i / PIX;
                const int pix = i - o * PIX;
                float a = pw_b[ed * NC + o];
                const float* wr = &s_pw[o * NC];
#pragma unroll 8
                for (int ic = 0; ic < NC; ic++) a += wr[ic] * s_dw[ic * PIX + pix];
                racc[k] += a;
            }
        }
        __syncthreads();
    }

    float* ob = outp + (size_t)(n * NCO + p * NC) * PIX;
#pragma unroll
    for (int k = 0; k < 13; k++) {
        int i = tid + k * 256;
        if (i < NC * PIX) ob[i] = racc[k];
    }
}

__global__ void __launch_bounds__(256) copy_kernel(
    const float* __restrict__ s, float* __restrict__ d)
{
    int i = blockIdx.x * 256 + threadIdx.x;
    d[i] = s[i];
}

// ---------------------------------------------------------------------------
extern "C" void kernel_launch(void* const* d_in, const int* in_sizes, int n_in,
                              void* d_out, int out_size)
{
    const float* x       = (const float*)d_in[0];
    const float* conv0_w = (const float*)d_in[1];
    const float* conv0_b = (const float*)d_in[2];
    const float* gn0_s   = (const float*)d_in[3];
    const float* gn0_b   = (const float*)d_in[4];
    const float* convs_w = (const float*)d_in[5];
    const float* convs_b = (const float*)d_in[6];
    const float* gns_s   = (const float*)d_in[7];
    const float* gns_b   = (const float*)d_in[8];
    const float* fo_dw_w = (const float*)d_in[9];
    const float* fo_dw_b = (const float*)d_in[10];
    const float* fo_pw_w = (const float*)d_in[11];
    const float* fo_pw_b = (const float*)d_in[12];
    const float* so_dw_w = (const float*)d_in[13];
    const float* so_dw_b = (const float*)d_in[14];
    const float* so_pw_w = (const float*)d_in[15];
    const float* so_pw_b = (const float*)d_in[16];
    float* out = (float*)d_out;

    float *pA, *pB;
    unsigned short *pColH, *pColL, *pActH, *pActL, *pX0H, *pX0L, *pW0H, *pW0L, *pWrH, *pWrL;
    cudaGetSymbolAddress((void**)&pA,    g_bufA);
    cudaGetSymbolAddress((void**)&pB,    g_bufB);
    cudaGetSymbolAddress((void**)&pColH, g_colh);
    cudaGetSymbolAddress((void**)&pColL, g_coll);
    cudaGetSymbolAddress((void**)&pActH, g_acth);
    cudaGetSymbolAddress((void**)&pActL, g_actl);
    cudaGetSymbolAddress((void**)&pX0H,  g_x0h);
    cudaGetSymbolAddress((void**)&pX0L,  g_x0l);
    cudaGetSymbolAddress((void**)&pW0H,  g_w0h);
    cudaGetSymbolAddress((void**)&pW0L,  g_w0l);
    cudaGetSymbolAddress((void**)&pWrH,  g_wrh);
    cudaGetSymbolAddress((void**)&pWrL,  g_wrl);

    const int SMEM_CONV = 3 * (2 * BM * SSTR + 2 * BN * SSTR) * 2;   // 92160 B
    cudaFuncSetAttribute(conv_gemm_kernel<KG0>,
                         cudaFuncAttributeMaxDynamicSharedMemorySize, SMEM_CONV);
    cudaFuncSetAttribute(conv_gemm_kernel<KGR>,
                         cudaFuncAttributeMaxDynamicSharedMemorySize, SMEM_CONV);

    // 1) split inputs & weights to bf16 hi/lo planes
    pack_x0_kernel<<<(NROI * CIN0 * 196) / 256, 256>>>(x);
    pack_split_kernel<<<(NCO * KG0) / 256, 256>>>(conv0_w, pW0H, pW0L);
    pack_split_kernel<<<(NREST * NCO * KGR) / 256, 256>>>(convs_w, pWrH, pWrL);

    dim3 cgrid(NCO / BN, MTOT / BM);   // (9, 196): n fastest -> A reuse in L2

    // 2) conv0 (stride 2 folded into im2col) + GN0/ReLU
    im2col_kernel<KG0, true><<<(MTOT * (KG0 / 4)) / 256, 256>>>(pX0H, pX0L, pColH, pColL);
    conv_gemm_kernel<KG0><<<cgrid, 256, SMEM_CONV>>>(pColH, pColL, pW0H, pW0L, conv0_b, pA);
    gn_relu_pack_kernel<<<NROI * NGROUP, 256>>>(pA, gn0_s, gn0_b, pActH, pActL);

    // 3) 7x [im2col + GEMM + GN/ReLU], ping-pong
    float* cur = pA;
    float* nxt = pB;
    for (int l = 0; l < NREST; l++) {
        im2col_kernel<KGR, false><<<(MTOT * (KGR / 4)) / 256, 256>>>(pActH, pActL, pColH, pColL);
        conv_gemm_kernel<KGR><<<cgrid, 256, SMEM_CONV>>>(
            pColH, pColL, pWrH + (size_t)l * NCO * KGR, pWrL + (size_t)l * NCO * KGR,
            convs_b + l * NCO, nxt);
        gn_relu_pack_kernel<<<NROI * NGROUP, 256>>>(nxt, gns_s + l * NCO, gns_b + l * NCO,
                                                    pActH, pActL);
        float* t = cur; cur = nxt; nxt = t;
    }
    // cur == final h, nxt free

    // 4) output half 1: h
    copy_kernel<<<HALF_OUT / 256, 256>>>(cur, out);

    // 5) first-order fusion -> nxt
    dim3 mgrid(NROI, NP);
    msg_pass_kernel<<<mgrid, 256>>>(cur, cur, fo_dw_w, fo_dw_b, fo_pw_w, fo_pw_b, nxt);

    // 6) second-order fusion -> output half 2
    msg_pass_kernel<<<mgrid, 256>>>(nxt, cur, so_dw_w, so_dw_b, so_pw_w, so_pw_b,
                                    out + HALF_OUT);
}

// round 7
// speedup vs baseline: 2.2836x; 1.1328x over previous
#include <cuda_runtime.h>
#include <cuda_bf16.h>
#include <cstdint>

// ---------------------------------------------------------------------------
// roi_grid_head, round 6: NHWC implicit GEMM (no im2col), mma.sync bf16
// hi/lo split (D = Ahi*Bhi + Ahi*Blo + Alo*Bhi, fp32 accum).
// Activations: [n][pad_pix][ch] u16 hi/lo planes; weights [co][tap*CIN+ci].
// 3-stage cp.async, ldmatrix fragments. GN/ReLU fused with NHWC repack.
// ---------------------------------------------------------------------------

#define NROI   512
#define CIN0   256
#define OHW    7
#define PIX    49
#define NCO    576
#define NP     9
#define NC     64
#define NREST  7
#define KG0    (CIN0 * 9)            // 2304
#define KGR    (NCO * 9)             // 5184
#define MTOT   (NROI * PIX)          // 25088 = 196*128
#define NGROUP 36
#define GSZ    784
#define HALF_OUT (NROI * NCO * PIX)  // 14450688

#define BM 128
#define BN 64
#define BK 32
#define SSTR 40                       // smem row stride in bf16 units (80B)

// __device__ scratch (zero-initialized; padded border pixels never written)
__device__ unsigned short g_acth[NROI * 81 * NCO];    // [n][9x9 pad][576]  47.8MB
__device__ unsigned short g_actl[NROI * 81 * NCO];
__device__ unsigned short g_x0h[NROI * 256 * CIN0];   // [n][16x16 pad][256] 67MB
__device__ unsigned short g_x0l[NROI * 256 * CIN0];
__device__ unsigned short g_w0h[NCO * KG0];           // [co][tap*256+ci]
__device__ unsigned short g_w0l[NCO * KG0];
__device__ unsigned short g_wrh[NREST * NCO * KGR];   // [l][co][tap*576+ci]
__device__ unsigned short g_wrl[NREST * NCO * KGR];
__device__ float g_bufA[HALF_OUT];
__device__ float g_bufB[HALF_OUT];

__constant__ int c_esrc[24]   = {1,3, 0,2,4, 1,5, 0,4,6, 1,3,5,7, 2,4,8, 3,7, 4,6,8, 5,7};
__constant__ int c_estart[10] = {0,2,5,7,10,14,17,19,22,24};

// ---------------------------------------------------------------------------
__device__ __forceinline__ void split_bf(float f, unsigned short& h, unsigned short& l) {
    __nv_bfloat16 bh = __float2bfloat16(f);
    float r = f - __bfloat162float(bh);
    h = __bfloat16_as_ushort(bh);
    l = __bfloat16_as_ushort(__float2bfloat16(r));
}

__device__ __forceinline__ void mma_bf16(float& c0, float& c1, float& c2, float& c3,
                                         uint32_t a0, uint32_t a1, uint32_t a2, uint32_t a3,
                                         uint32_t b0, uint32_t b1) {
    asm volatile(
        "mma.sync.aligned.m16n8k16.row.col.f32.bf16.bf16.f32 "
        "{%0,%1,%2,%3},{%4,%5,%6,%7},{%8,%9},{%0,%1,%2,%3};\n"
        : "+f"(c0), "+f"(c1), "+f"(c2), "+f"(c3)
        : "r"(a0), "r"(a1), "r"(a2), "r"(a3), "r"(b0), "r"(b1));
}

__device__ __forceinline__ void ldmx4(uint32_t& r0, uint32_t& r1, uint32_t& r2, uint32_t& r3,
                                      uint32_t addr) {
    asm volatile("ldmatrix.sync.aligned.m8n8.x4.shared.b16 {%0,%1,%2,%3},[%4];\n"
                 : "=r"(r0), "=r"(r1), "=r"(r2), "=r"(r3) : "r"(addr));
}

__device__ __forceinline__ void cp16(uint32_t daddr, const void* src) {
    asm volatile("cp.async.cg.shared.global [%0], [%1], 16;\n" :: "r"(daddr), "l"(src));
}
__device__ __forceinline__ void cp_commit() { asm volatile("cp.async.commit_group;\n" ::: "memory"); }
__device__ __forceinline__ void cp_wait1()  { asm volatile("cp.async.wait_group 1;\n" ::: "memory"); }

// ---------------------------------------------------------------------------
// Packing kernels
// ---------------------------------------------------------------------------
// x: [n][256][14][14] -> NHWC padded 16x16 planes. Block = (n, 32-ch group).
__global__ void __launch_bounds__(256) pack_x0_kernel(const float* __restrict__ x) {
    __shared__ float sx[32 * 196];
    const int n  = blockIdx.x;
    const int c0 = blockIdx.y * 32;
    const int tid = threadIdx.x;
    for (int idx = tid; idx < 32 * 196; idx += 256) {
        int c = idx / 196, pix = idx - c * 196;
        sx[idx] = x[((size_t)(n * CIN0 + c0 + c)) * 196 + pix];
    }
    __syncthreads();
    for (int idx = tid; idx < 196 * 32; idx += 256) {
        int pix = idx >> 5, cl = idx & 31;
        int y = pix / 14, xx = pix - y * 14;
        unsigned short h, l;
        split_bf(sx[cl * 196 + pix], h, l);
        size_t o = ((size_t)(n * 256) + (y + 1) * 16 + (xx + 1)) * CIN0 + c0 + cl;
        g_x0h[o] = h; g_x0l[o] = l;
    }
}

// conv0 weights: [co][ci][3][3] -> [co][tap*256+ci]
__global__ void __launch_bounds__(256) pack_w0_kernel(const float* __restrict__ w) {
    int i = blockIdx.x * 256 + threadIdx.x;       // NCO*KG0
    int co = i / KG0, r = i - co * KG0;
    int tap = r / CIN0, ci = r - tap * CIN0;
    unsigned short h, l;
    split_bf(w[(size_t)(co * CIN0 + ci) * 9 + tap], h, l);
    g_w0h[i] = h; g_w0l[i] = l;
}

// conv weights: [l][co][ci][3][3] -> [l][co][tap*576+ci]
__global__ void __launch_bounds__(256) pack_wr_kernel(const float* __restrict__ w) {
    int i = blockIdx.x * 256 + threadIdx.x;       // NREST*NCO*KGR
    const int per = NCO * KGR;
    int lyr = i / per, rr = i - lyr * per;
    int co = rr / KGR, r = rr - co * KGR;
    int tap = r / NCO, ci = r - tap * NCO;
    unsigned short h, l;
    split_bf(w[((size_t)(lyr * NCO + co) * NCO + ci) * 9 + tap], h, l);
    g_wrh[i] = h; g_wrl[i] = l;
}

// ---------------------------------------------------------------------------
// NHWC implicit-GEMM conv: out[m][co] = sum_k A[m][k]*B[co][k],
// k = tap*CPT + ci, A gathered from padded NHWC planes.
// BM=128 BN=64 BK=32, 3-stage cp.async, ldmatrix, hi/lo 3-stream mma.
// ---------------------------------------------------------------------------
template<int CPT, int PITCH, int S, int K>
__global__ void __launch_bounds__(256, 2) conv_gemm_kernel(
    const unsigned short* __restrict__ Ah, const unsigned short* __restrict__ Al,
    const unsigned short* __restrict__ Bgh, const unsigned short* __restrict__ Bgl,
    const float* __restrict__ bias, float* __restrict__ out)
{
    extern __shared__ unsigned short smem[];
    constexpr int A_SZ  = BM * SSTR;
    constexpr int B_SZ  = BN * SSTR;
    constexpr int STG   = 2 * A_SZ + 2 * B_SZ;
    constexpr int T     = K / BK;
    constexpr int CPT32 = CPT / BK;
    constexpr int NPIXP = PITCH * PITCH;

    const int tid  = threadIdx.x;
    const int lane = tid & 31;
    const int warp = tid >> 5;
    const int wm = warp >> 1, wn = warp & 1;
    const int grp = lane >> 2, tg = lane & 3;
    const int co0 = blockIdx.x * BN;
    const int m0  = blockIdx.y * BM;

    const uint32_t smem_b = (uint32_t)__cvta_generic_to_shared(smem);

    // A loader: row ar = tid>>1, k-offset ac in {0,16}
    const int ar = tid >> 1;
    const int ac = (tid & 1) * 16;
    {
    }
    const int am   = m0 + ar;
    const int nimg = am / PIX;
    const int apix = am - nimg * PIX;
    const int ay   = apix / OHW, ax = apix - ay * OHW;
    const unsigned short* rowH = Ah + ((size_t)nimg * NPIXP
                                       + (size_t)(S * ay) * PITCH + (S * ax)) * CPT;
    const unsigned short* rowL = Al + ((size_t)nimg * NPIXP
                                       + (size_t)(S * ay) * PITCH + (S * ax)) * CPT;
    // B loader: row br = tid&63, k-offset bc in {0,8,16,24}
    const int br = tid & 63;
    const int bc = (tid >> 6) * 8;
    const unsigned short* Bgh_p = Bgh + (size_t)(co0 + br) * K;
    const unsigned short* Bgl_p = Bgl + (size_t)(co0 + br) * K;
    const uint32_t sAo = (uint32_t)(ar * SSTR * 2);
    const uint32_t sBo = (uint32_t)(br * SSTR * 2);

    // ldmatrix per-thread byte offsets within plane
    const uint32_t offA = (uint32_t)(((wm * 32 + (lane & 15)) * SSTR + 8 * (lane >> 4)) * 2);
    const uint32_t offB = (uint32_t)(((wn * 32 + (lane & 7) + 8 * (lane >> 4)) * SSTR
                                      + 8 * ((lane >> 3) & 1)) * 2);

    float acc[2][4][4];
#pragma unroll
    for (int a = 0; a < 2; a++)
#pragma unroll
        for (int b = 0; b < 4; b++)
#pragma unroll
            for (int c = 0; c < 4; c++) acc[a][b][c] = 0.f;

#define ISSUE(t_)                                                              \
    do {                                                                       \
        int t__ = (t_);                                                        \
        if (t__ < T) {                                                         \
            const uint32_t sb = smem_b + (uint32_t)((t__ % 3) * STG) * 2;      \
            const int tap__ = t__ / CPT32;                                     \
            const int rem__ = t__ - tap__ * CPT32;                             \
            const int ky__  = tap__ / 3;                                       \
            const int kx__  = tap__ - ky__ * 3;                                \
            const int poff__ = (ky__ * PITCH + kx__) * CPT + rem__ * BK + ac;  \
            cp16(sb + sAo + ac * 2,       rowH + poff__);                      \
            cp16(sb + sAo + (ac + 8) * 2, rowH + poff__ + 8);                  \
            cp16(sb + A_SZ * 2 + sAo + ac * 2,       rowL + poff__);           \
            cp16(sb + A_SZ * 2 + sAo + (ac + 8) * 2, rowL + poff__ + 8);       \
            const int kt__ = t__ * BK;                                         \
            cp16(sb + 2 * A_SZ * 2 + sBo + bc * 2,          Bgh_p + kt__ + bc);\
            cp16(sb + (2 * A_SZ + B_SZ) * 2 + sBo + bc * 2, Bgl_p + kt__ + bc);\
        }                                                                      \
        cp_commit();                                                           \
    } while (0)

    ISSUE(0);
    ISSUE(1);

    for (int t = 0; t < T; t++) {
        cp_wait1();
        __syncthreads();
        ISSUE(t + 2);

        const uint32_t aH = smem_b + (uint32_t)((t % 3) * STG) * 2;
        const uint32_t aL = aH + A_SZ * 2;
        const uint32_t bH = aH + 2 * A_SZ * 2;
        const uint32_t bL = bH + B_SZ * 2;

#pragma unroll
        for (int h = 0; h < BK; h += 16) {
            uint32_t Af[2][4], Lf[2][4], Bf[4][2], Mf[4][2];
#pragma unroll
            for (int mi = 0; mi < 2; mi++) {
                const uint32_t d = offA + (uint32_t)((mi * 16 * SSTR + h) * 2);
                ldmx4(Af[mi][0], Af[mi][1], Af[mi][2], Af[mi][3], aH + d);
                ldmx4(Lf[mi][0], Lf[mi][1], Lf[mi][2], Lf[mi][3], aL + d);
            }
#pragma unroll
            for (int np = 0; np < 2; np++) {
                const uint32_t d = offB + (uint32_t)((np * 16 * SSTR + h) * 2);
                ldmx4(Bf[2*np][0], Bf[2*np][1], Bf[2*np+1][0], Bf[2*np+1][1], bH + d);
                ldmx4(Mf[2*np][0], Mf[2*np][1], Mf[2*np+1][0], Mf[2*np+1][1], bL + d);
            }
#pragma unroll
            for (int mi = 0; mi < 2; mi++)
#pragma unroll
                for (int ni = 0; ni < 4; ni++) {
                    float* c = acc[mi][ni];
                    mma_bf16(c[0], c[1], c[2], c[3],
                             Af[mi][0], Af[mi][1], Af[mi][2], Af[mi][3],
                             Bf[ni][0], Bf[ni][1]);
                    mma_bf16(c[0], c[1], c[2], c[3],
                             Af[mi][0], Af[mi][1], Af[mi][2], Af[mi][3],
                             Mf[ni][0], Mf[ni][1]);
                    mma_bf16(c[0], c[1], c[2], c[3],
                             Lf[mi][0], Lf[mi][1], Lf[mi][2], Lf[mi][3],
                             Bf[ni][0], Bf[ni][1]);
                }
        }
    }
#undef ISSUE

    // epilogue: out NCHW
#pragma unroll
    for (int mi = 0; mi < 2; mi++) {
#pragma unroll
        for (int half = 0; half < 2; half++) {
            int m    = m0 + wm * 32 + mi * 16 + grp + 8 * half;
            int nimg2 = m / PIX;
            int pix2  = m - nimg2 * PIX;
            float* ob = out + (size_t)(nimg2 * NCO) * PIX + pix2;
#pragma unroll
            for (int ni = 0; ni < 4; ni++) {
                int co = co0 + wn * 32 + ni * 8 + 2 * tg;
                float b0 = __ldg(&bias[co]);
                float b1 = __ldg(&bias[co + 1]);
                ob[(size_t)co * PIX]       = acc[mi][ni][2 * half]     + b0;
                ob[(size_t)(co + 1) * PIX] = acc[mi][ni][2 * half + 1] + b1;
            }
        }
    }
}

// ---------------------------------------------------------------------------
// GroupNorm + affine + ReLU (in-place fp32 NCHW) + NHWC hi/lo repack with
// sector-aligned 32B writes. One block per (n, group).
// ---------------------------------------------------------------------------
__global__ void __launch_bounds__(256) gn_relu_pack_kernel(
    float* __restrict__ buf, const float* __restrict__ sc, const float* __restrict__ bi,
    unsigned short* __restrict__ ph, unsigned short* __restrict__ pl)
{
    const int blk = blockIdx.x;
    const int n   = blk / NGROUP;
    const int g   = blk - n * NGROUP;
    float* base = buf + (size_t)blk * GSZ;
    const int tid = threadIdx.x;

    __shared__ float s_vals[GSZ];
    __shared__ float r1[8], r2[8];
    __shared__ float s_mu, s_inv;

    float vals[4];
    int cnt = 0;
    float s1 = 0.f, s2 = 0.f;
    for (int e = tid; e < GSZ; e += 256) {
        float x = base[e];
        vals[cnt++] = x;
        s1 += x; s2 += x * x;
    }
#pragma unroll
    for (int o = 16; o > 0; o >>= 1) {
        s1 += __shfl_xor_sync(0xffffffff, s1, o);
        s2 += __shfl_xor_sync(0xffffffff, s2, o);
    }
    const int w = tid >> 5, lane = tid & 31;
    if (lane == 0) { r1[w] = s1; r2[w] = s2; }
    __syncthreads();
    if (tid == 0) {
        float a = 0.f, b = 0.f;
#pragma unroll
        for (int i = 0; i < 8; i++) { a += r1[i]; b += r2[i]; }
        float mu  = a * (1.f / GSZ);
        float var = b * (1.f / GSZ) - mu * mu;
        s_mu = mu;
        s_inv = rsqrtf(var + 1e-5f);
    }
    __syncthreads();
    const float mu = s_mu, inv = s_inv;
    cnt = 0;
    for (int e = tid; e < GSZ; e += 256) {
        const int chl = e / PIX;
        const int ch  = g * 16 + chl;
        float y = (vals[cnt++] - mu) * inv * sc[ch] + bi[ch];
        y = fmaxf(y, 0.f);
        base[e] = y;
        s_vals[e] = y;
    }
    __syncthreads();

    if (tid < PIX) {
        const int py = tid / OHW, px = tid - py * OHW;
        uint32_t hw[8], lw[8];
#pragma unroll
        for (int j = 0; j < 8; j++) {
            unsigned short h0, l0, h1, l1;
            split_bf(s_vals[(2 * j) * PIX + tid], h0, l0);
            split_bf(s_vals[(2 * j + 1) * PIX + tid], h1, l1);
            hw[j] = (uint32_t)h0 | ((uint32_t)h1 << 16);
            lw[j] = (uint32_t)l0 | ((uint32_t)l1 << 16);
        }
        size_t o = ((size_t)(n * 81) + (py + 1) * 9 + (px + 1)) * NCO + g * 16;
        *(uint4*)(ph + o)     = make_uint4(hw[0], hw[1], hw[2], hw[3]);
        *(uint4*)(ph + o + 8) = make_uint4(hw[4], hw[5], hw[6], hw[7]);
        *(uint4*)(pl + o)     = make_uint4(lw[0], lw[1], lw[2], lw[3]);
        *(uint4*)(pl + o + 8) = make_uint4(lw[4], lw[5], lw[6], lw[7]);
    }
}

// ---------------------------------------------------------------------------
// Message passing, dst-major (unchanged).
// ---------------------------------------------------------------------------
__global__ void __launch_bounds__(256) msg_pass_kernel(
    const float* __restrict__ src_feat, const float* __restrict__ pts,
    const float* __restrict__ dw_w, const float* __restrict__ dw_b,
    const float* __restrict__ pw_w, const float* __restrict__ pw_b,
    float* __restrict__ outp)
{
    const int n = blockIdx.x;
    const int p = blockIdx.y;
    const int tid = threadIdx.x;

    __shared__ float s_in[NC * PIX];
    __shared__ float s_dw[NC * PIX];
    __shared__ float s_pw[NC * NC];

    float racc[13];
    const float* ptsb = pts + (size_t)(n * NCO + p * NC) * PIX;
#pragma unroll
    for (int k = 0; k < 13; k++) {
        int i = tid + k * 256;
        if (i < NC * PIX) racc[k] = ptsb[i];
    }

    const int e0 = c_estart[p], e1 = c_estart[p + 1];
    for (int ed = e0; ed < e1; ed++) {
        const int q = c_esrc[ed];
        const float* sb = src_feat + (size_t)(n * NCO + q * NC) * PIX;
        for (int i = tid; i < NC * PIX; i += 256) s_in[i] = sb[i];
        for (int i = tid; i < NC * NC; i += 256) s_pw[i] = pw_w[ed * NC * NC + i];
        __syncthreads();

        for (int i = tid; i < NC * PIX; i += 256) {
            const int c = i / PIX;
            const int pix = i - c * PIX;
            const int y = pix / OHW, x = pix - y * OHW;
            const float* wv = dw_w + (ed * NC + c) * 25;
            float a = dw_b[ed * NC + c];
#pragma unroll
            for (int dy = 0; dy < 5; dy++) {
                const int yy = y + dy - 2;
                if ((unsigned)yy < (unsigned)OHW) {
#pragma unroll
                    for (int dx = 0; dx < 5; dx++) {
                        const int xx = x + dx - 2;
                        if ((unsigned)xx < (unsigned)OHW)
                            a += wv[dy * 5 + dx] * s_in[c * PIX + yy * OHW + xx];
                    }
                }
            }
            s_dw[i] = a;
        }
        __syncthreads();

#pragma unroll
        for (int k = 0; k < 13; k++) {
            const int i = tid + k * 256;
            if (i < NC * PIX) {
                const int o = i / PIX;
                const int pix = i - o * PIX;
                float a = pw_b[ed * NC + o];
                const float* wr = &s_pw[o * NC];
#pragma unroll 8
                for (int ic = 0; ic < NC; ic++) a += wr[ic] * s_dw[ic * PIX + pix];
                racc[k] += a;
            }
        }
        __syncthreads();
    }

    float* ob = outp + (size_t)(n * NCO + p * NC) * PIX;
#pragma unroll
    for (int k = 0; k < 13; k++) {
        int i = tid + k * 256;
        if (i < NC * PIX) ob[i] = racc[k];
    }
}

__global__ void __launch_bounds__(256) copy_kernel(
    const float* __restrict__ s, float* __restrict__ d)
{
    int i = blockIdx.x * 256 + threadIdx.x;
    d[i] = s[i];
}

// ---------------------------------------------------------------------------
extern "C" void kernel_launch(void* const* d_in, const int* in_sizes, int n_in,
                              void* d_out, int out_size)
{
    const float* x       = (const float*)d_in[0];
    const float* conv0_w = (const float*)d_in[1];
    const float* conv0_b = (const float*)d_in[2];
    const float* gn0_s   = (const float*)d_in[3];
    const float* gn0_b   = (const float*)d_in[4];
    const float* convs_w = (const float*)d_in[5];
    const float* convs_b = (const float*)d_in[6];
    const float* gns_s   = (const float*)d_in[7];
    const float* gns_b   = (const float*)d_in[8];
    const float* fo_dw_w = (const float*)d_in[9];
    const float* fo_dw_b = (const float*)d_in[10];
    const float* fo_pw_w = (const float*)d_in[11];
    const float* fo_pw_b = (const float*)d_in[12];
    const float* so_dw_w = (const float*)d_in[13];
    const float* so_dw_b = (const float*)d_in[14];
    const float* so_pw_w = (const float*)d_in[15];
    const float* so_pw_b = (const float*)d_in[16];
    float* out = (float*)d_out;

    float *pA, *pB;
    unsigned short *pActH, *pActL, *pX0H, *pX0L, *pW0H, *pW0L, *pWrH, *pWrL;
    cudaGetSymbolAddress((void**)&pA,    g_bufA);
    cudaGetSymbolAddress((void**)&pB,    g_bufB);
    cudaGetSymbolAddress((void**)&pActH, g_acth);
    cudaGetSymbolAddress((void**)&pActL, g_actl);
    cudaGetSymbolAddress((void**)&pX0H,  g_x0h);
    cudaGetSymbolAddress((void**)&pX0L,  g_x0l);
    cudaGetSymbolAddress((void**)&pW0H,  g_w0h);
    cudaGetSymbolAddress((void**)&pW0L,  g_w0l);
    cudaGetSymbolAddress((void**)&pWrH,  g_wrh);
    cudaGetSymbolAddress((void**)&pWrL,  g_wrl);

    const int SMEM_CONV = 3 * (2 * BM * SSTR + 2 * BN * SSTR) * 2;   // 92160 B
    cudaFuncSetAttribute((const void*)conv_gemm_kernel<CIN0, 16, 2, KG0>,
                         cudaFuncAttributeMaxDynamicSharedMemorySize, SMEM_CONV);
    cudaFuncSetAttribute((const void*)conv_gemm_kernel<NCO, 9, 1, KGR>,
                         cudaFuncAttributeMaxDynamicSharedMemorySize, SMEM_CONV);

    // 1) pack inputs & weights (NHWC / tap-major)
    pack_x0_kernel<<<dim3(NROI, CIN0 / 32), 256>>>(x);
    pack_w0_kernel<<<(NCO * KG0) / 256, 256>>>(conv0_w);
    pack_wr_kernel<<<(NREST * NCO * KGR) / 256, 256>>>(convs_w);

    dim3 cgrid(NCO / BN, MTOT / BM);   // (9, 196): co fastest -> A L2 reuse

    // 2) conv0 (stride 2) + GN0/ReLU(+repack)
    conv_gemm_kernel<CIN0, 16, 2, KG0><<<cgrid, 256, SMEM_CONV>>>(
        pX0H, pX0L, pW0H, pW0L, conv0_b, pA);
    gn_relu_pack_kernel<<<NROI * NGROUP, 256>>>(pA, gn0_s, gn0_b, pActH, pActL);

    // 3) 7x [conv + GN/ReLU(+repack)], ping-pong
    float* cur = pA;
    float* nxt = pB;
    for (int l = 0; l < NREST; l++) {
        conv_gemm_kernel<NCO, 9, 1, KGR><<<cgrid, 256, SMEM_CONV>>>(
            pActH, pActL, pWrH + (size_t)l * NCO * KGR, pWrL + (size_t)l * NCO * KGR,
            convs_b + l * NCO, nxt);
        gn_relu_pack_kernel<<<NROI * NGROUP, 256>>>(nxt, gns_s + l * NCO, gns_b + l * NCO,
                                                    pActH, pActL);
        float* t = cur; cur = nxt; nxt = t;
    }
    // cur == final h, nxt free

    // 4) output half 1: h
    copy_kernel<<<HALF_OUT / 256, 256>>>(cur, out);

    // 5) first-order fusion -> nxt
    dim3 mgrid(NROI, NP);
    msg_pass_kernel<<<mgrid, 256>>>(cur, cur, fo_dw_w, fo_dw_b, fo_pw_w, fo_pw_b, nxt);

    // 6) second-order fusion -> output half 2
    msg_pass_kernel<<<mgrid, 256>>>(nxt, cur, so_dw_w, so_dw_b, so_pw_w, so_pw_b,
                                    out + HALF_OUT);
}